// round 14
// baseline (speedup 1.0000x reference)
#include <cuda_runtime.h>
#include <math.h>
#include <stdint.h>

#define NN 50000
#define E_RAW 800000
#define E_TOT (E_RAW + NN)

// ---------------- scratch ----------------
__device__ float g_bufA[(size_t)NN * 256];
__device__ float g_bufB[(size_t)NN * 256];
__device__ float g_s[NN * 4];
__device__ float g_d[NN * 4];
__device__ int   g_counts[NN];
__device__ int   g_row_ptr[NN + 1];
__device__ int   g_row_fill[NN];
__device__ int   g_col_src[E_TOT];
__device__ unsigned g_smax_u[12];   // 4 slots per layer

// ---------------- CSR build ----------------
__global__ void k_build_count(const int* __restrict__ ei) {
    int e = blockIdx.x * blockDim.x + threadIdx.x;
    if (e >= E_TOT) return;
    int dst = (e < E_RAW) ? ei[E_RAW + e] : (e - E_RAW);
    atomicAdd(&g_counts[dst], 1);
}

__global__ void k_scan() {
    const int CH = (NN + 1023) / 1024;
    int t = threadIdx.x;
    int lane = t & 31, warp = t >> 5;
    int beg = t * CH;
    int end = min(beg + CH, NN);
    int s = 0;
    for (int i = beg; i < end; i++) s += g_counts[i];

    int v = s;
#pragma unroll
    for (int off = 1; off < 32; off <<= 1) {
        int u = __shfl_up_sync(0xffffffffu, v, off);
        if (lane >= off) v += u;
    }
    __shared__ int wsum[32];
    if (lane == 31) wsum[warp] = v;
    __syncthreads();
    if (warp == 0) {
        int w = wsum[lane];
#pragma unroll
        for (int off = 1; off < 32; off <<= 1) {
            int u = __shfl_up_sync(0xffffffffu, w, off);
            if (lane >= off) w += u;
        }
        wsum[lane] = w;
    }
    __syncthreads();
    int excl = v - s + (warp ? wsum[warp - 1] : 0);

    int p = excl;
    for (int i = beg; i < end; i++) {
        g_row_fill[i] = p;
        p += g_counts[i];
        g_row_ptr[i + 1] = p;
    }
    if (t == 0) g_row_ptr[0] = 0;
}

__global__ void k_scatter(const int* __restrict__ ei) {
    int e = blockIdx.x * blockDim.x + threadIdx.x;
    if (e >= E_TOT) return;
    int s_, d_;
    if (e < E_RAW) { s_ = ei[e]; d_ = ei[E_RAW + e]; }
    else           { s_ = d_ = e - E_RAW; }
    int pos = atomicAdd(&g_row_fill[d_], 1);
    g_col_src[pos] = s_;
}

// ---------------- tf32 tensor-core GEMM, double-buffered, fragment-major A ----------------
__device__ __forceinline__ uint32_t f2tf32(float x) {
    uint32_t r;
    asm("cvt.rna.tf32.f32 %0, %1;" : "=r"(r) : "f"(x));
    return r;
}

__device__ __forceinline__ void mma_tf32(float* c, const uint32_t* a, const uint32_t* b) {
    asm volatile(
        "mma.sync.aligned.m16n8k8.row.col.f32.tf32.tf32.f32 "
        "{%0,%1,%2,%3}, {%4,%5,%6,%7}, {%8,%9}, {%0,%1,%2,%3};"
        : "+f"(c[0]), "+f"(c[1]), "+f"(c[2]), "+f"(c[3])
        : "r"(a[0]), "r"(a[1]), "r"(a[2]), "r"(a[3]), "r"(b[0]), "r"(b[1]));
}

// C[N,M] = A[N,K] @ B[K,M]; tile 128x64, K-step 32, 8 warps.
// A tile in fragment-major smem: word = mi16*512 + kt*128 + ((g*4+t)^kt)*4 + vec,
//   vec = half + 2*khalf  (half: row+8, khalf: k+4). One LDS.128 per MMA A-fragment.
__global__ void k_gemm_tc(const float* __restrict__ A, const float* __restrict__ B,
                          float* __restrict__ C, int N, int K, int M) {
    __shared__ __align__(16) uint32_t AsF[2][4096];     // 16KB per buffer
    __shared__ __align__(16) uint32_t Bs[2][32][68];    // padded row layout

    int tid = threadIdx.x;
    int lane = tid & 31, wid = tid >> 5;
    int warp_m = wid & 1, warp_n = wid >> 1;
    int g = lane >> 2, t = lane & 3;
    int rowBase = blockIdx.y * 128, colBase = blockIdx.x * 64;

    float acc[4][2][4] = {};
    float4 ra[4], rb[2];

    // A staging addresses: load i covers row a_r[i], k-offsets a_c[i]..a_c[i]+3
    int a_r[4], a_base[4], a_kt[4];
    int b_r[2], b_c[2];
#pragma unroll
    for (int i = 0; i < 4; i++) {
        int idx = tid + i * 256;
        int r = idx >> 3;
        int k0 = (idx & 7) * 4;
        a_r[i] = r;
        int gg = r & 7, half = (r >> 3) & 1, mi16 = r >> 4;
        int kt = k0 >> 3, khalf = (k0 >> 2) & 1;
        int vec = half + 2 * khalf;
        a_kt[i] = kt;
        a_base[i] = mi16 * 512 + kt * 128 + gg * 16 + vec;  // + (t^kt)*4 at store
    }
#pragma unroll
    for (int i = 0; i < 2; i++) {
        int idx = tid + i * 256;
        b_r[i] = idx >> 4; b_c[i] = (idx & 15) * 4;
    }

#define LOAD_TILE(kb)                                                              \
    {                                                                              \
        _Pragma("unroll")                                                          \
        for (int i = 0; i < 4; i++) {                                              \
            int gr = rowBase + a_r[i];                                             \
            int kc = ((tid + i * 256) & 7) * 4;                                    \
            ra[i] = (gr < N) ? *(const float4*)(A + (size_t)gr * K + (kb) + kc)    \
                             : make_float4(0.f, 0.f, 0.f, 0.f);                    \
        }                                                                          \
        _Pragma("unroll")                                                          \
        for (int i = 0; i < 2; i++)                                                \
            rb[i] = *(const float4*)(B + (size_t)((kb) + b_r[i]) * M + colBase + b_c[i]); \
    }

#define STORE_TILE(buf)                                                            \
    {                                                                              \
        _Pragma("unroll")                                                          \
        for (int i = 0; i < 4; i++) {                                              \
            int kt = a_kt[i], base = a_base[i];                                    \
            AsF[buf][base + ((0 ^ kt) << 2)] = f2tf32(ra[i].x);                    \
            AsF[buf][base + ((1 ^ kt) << 2)] = f2tf32(ra[i].y);                    \
            AsF[buf][base + ((2 ^ kt) << 2)] = f2tf32(ra[i].z);                    \
            AsF[buf][base + ((3 ^ kt) << 2)] = f2tf32(ra[i].w);                    \
        }                                                                          \
        _Pragma("unroll")                                                          \
        for (int i = 0; i < 2; i++) {                                              \
            uint4 u;                                                               \
            u.x = f2tf32(rb[i].x); u.y = f2tf32(rb[i].y);                          \
            u.z = f2tf32(rb[i].z); u.w = f2tf32(rb[i].w);                          \
            *(uint4*)&Bs[buf][b_r[i]][b_c[i]] = u;                                 \
        }                                                                          \
    }

    LOAD_TILE(0);
    STORE_TILE(0);
    __syncthreads();

    int nk = K >> 5;
    for (int ik = 0; ik < nk; ik++) {
        int cur = ik & 1;
        if (ik + 1 < nk) LOAD_TILE((ik + 1) << 5);

#pragma unroll
        for (int kt = 0; kt < 4; kt++) {
            int kk = kt << 3;
            uint32_t bf[2][2];
#pragma unroll
            for (int ni = 0; ni < 2; ni++) {
                int col = warp_n * 16 + ni * 8 + g;
                bf[ni][0] = Bs[cur][kk + t][col];
                bf[ni][1] = Bs[cur][kk + t + 4][col];
            }
#pragma unroll
            for (int mi = 0; mi < 4; mi++) {
                int idx = (warp_m * 4 + mi) * 512 + kt * 128 + ((lane ^ kt) << 2);
                uint4 av = *(const uint4*)&AsF[cur][idx];
                uint32_t af[4] = {av.x, av.y, av.z, av.w};
#pragma unroll
                for (int ni = 0; ni < 2; ni++)
                    mma_tf32(acc[mi][ni], af, bf[ni]);
            }
        }
        if (ik + 1 < nk) {
            STORE_TILE(cur ^ 1);
            __syncthreads();
        }
    }

#pragma unroll
    for (int mi = 0; mi < 4; mi++) {
#pragma unroll
        for (int ni = 0; ni < 2; ni++) {
            int r0 = rowBase + warp_m * 64 + mi * 16 + g;
            int c0 = colBase + warp_n * 16 + ni * 8 + 2 * t;
            if (r0 < N)
                *(float2*)(C + (size_t)r0 * M + c0) = make_float2(acc[mi][ni][0], acc[mi][ni][1]);
            if (r0 + 8 < N)
                *(float2*)(C + (size_t)(r0 + 8) * M + c0) = make_float2(acc[mi][ni][2], acc[mi][ni][3]);
        }
    }
#undef LOAD_TILE
#undef STORE_TILE
}

// ---------------- per-node attention scores ----------------
__global__ void k_scores(const float* __restrict__ xp, const float* __restrict__ a_src,
                         const float* __restrict__ a_dst, float* __restrict__ s,
                         float* __restrict__ d, int H, int C) {
    int gw = (blockIdx.x * blockDim.x + threadIdx.x) >> 5;
    int lane = threadIdx.x & 31;
    if (gw >= NN * H) return;
    int n = gw / H, h = gw - n * H;
    const float* row = xp + (size_t)n * H * C + h * C;
    float ss = 0.f, dd = 0.f;
    for (int c = lane; c < C; c += 32) {
        float v = row[c];
        ss += v * a_src[h * C + c];
        dd += v * a_dst[h * C + c];
    }
#pragma unroll
    for (int off = 16; off; off >>= 1) {
        ss += __shfl_xor_sync(0xffffffffu, ss, off);
        dd += __shfl_xor_sync(0xffffffffu, dd, off);
    }
    if (lane == 0) { s[n * H + h] = ss; d[n * H + h] = dd; }
}

// ---------------- global per-head max of s ----------------
__device__ __forceinline__ unsigned f_enc(float x) {
    unsigned b = __float_as_uint(x);
    return (b & 0x80000000u) ? ~b : (b | 0x80000000u);
}
__device__ __forceinline__ float f_dec(unsigned u) {
    unsigned b = (u & 0x80000000u) ? (u & 0x7FFFFFFFu) : ~u;
    return __uint_as_float(b);
}

template <int H>
__global__ void k_smax(const float* __restrict__ s, int slot) {
    const unsigned FULL = 0xffffffffu;
    int total4 = (H == 4) ? NN : NN / 4;
    float mx[4] = {-1e30f, -1e30f, -1e30f, -1e30f};
    for (int i = blockIdx.x * blockDim.x + threadIdx.x; i < total4; i += gridDim.x * blockDim.x) {
        float4 v = ((const float4*)s)[i];
        mx[0] = fmaxf(mx[0], v.x);
        mx[1] = fmaxf(mx[1], v.y);
        mx[2] = fmaxf(mx[2], v.z);
        mx[3] = fmaxf(mx[3], v.w);
    }
    if (H == 1) {
        mx[0] = fmaxf(fmaxf(mx[0], mx[1]), fmaxf(mx[2], mx[3]));
    }
    int lane = threadIdx.x & 31;
#pragma unroll
    for (int h = 0; h < H; h++) {
#pragma unroll
        for (int off = 16; off; off >>= 1)
            mx[h] = fmaxf(mx[h], __shfl_xor_sync(FULL, mx[h], off));
        if (lane == 0) atomicMax(&g_smax_u[slot + h], f_enc(mx[h]));
    }
}

__global__ void k_smax_reset() {
    if (threadIdx.x < 12) g_smax_u[threadIdx.x] = 0u;
}

// ---------------- aggregation: one WARP per node (R12 structure) ----------------
template <int H, int C, bool ELU>
__global__ void k_agg_warp(const float* __restrict__ xp, const float* __restrict__ sarr,
                           const float* __restrict__ darr, const float* __restrict__ bias,
                           float* __restrict__ out, int slot) {
    constexpr int CH = H * C;
    constexpr int PL = CH / 32;
    constexpr int V  = PL / 4;
    const unsigned FULL = 0xffffffffu;

    __shared__ float al_sh[8][32 * H];
    __shared__ int   sr_sh[8][32];

    int warp = threadIdx.x >> 5, lane = threadIdx.x & 31;
    int n = blockIdx.x * 8 + warp;
    if (n >= NN) return;

    int beg = g_row_ptr[n];
    int deg = g_row_ptr[n + 1] - beg;

    float dn[H];
    if (H == 4) {
        float4 t4 = ((const float4*)darr)[n];
        dn[0] = t4.x; dn[1] = t4.y; dn[2] = t4.z; dn[3] = t4.w;
    } else {
        dn[0] = darr[n];
    }

    float mx[H];
#pragma unroll
    for (int h = 0; h < H; h++) {
        float e = f_dec(g_smax_u[slot + h]) + dn[h];
        mx[h] = e > 0.f ? e : 0.2f * e;
    }

    const int hsel = (lane * PL) / C;
    const float* xbase = xp + lane * PL;
    float zh[H];
#pragma unroll
    for (int h = 0; h < H; h++) zh[h] = 0.f;
    float4 acc[V];
#pragma unroll
    for (int v = 0; v < V; v++) acc[v] = make_float4(0.f, 0.f, 0.f, 0.f);

    for (int base = 0; base < deg; base += 32) {
        int idx = base + lane;
        if (idx < deg) {
            int srl = g_col_src[beg + idx];
            sr_sh[warp][lane] = srl;
            float ev[H];
            if (H == 4) {
                float4 sv = ((const float4*)sarr)[srl];
                ev[0] = sv.x; ev[1] = sv.y; ev[2] = sv.z; ev[3] = sv.w;
            } else {
                ev[0] = sarr[srl];
            }
#pragma unroll
            for (int h = 0; h < H; h++) {
                float e = ev[h] + dn[h];
                e = e > 0.f ? e : 0.2f * e;
                float p = __expf(e - mx[h]);
                al_sh[warp][lane * H + h] = p;
                zh[h] += p;
            }
        }
        __syncwarp();
        int cnt = min(32, deg - base);

        float a_nxt = al_sh[warp][0 * H + hsel];
        {
            int sr0 = sr_sh[warp][0];
            const float4* r = (const float4*)(xbase + (size_t)sr0 * CH);
            float4 x_nxt[V];
#pragma unroll
            for (int v = 0; v < V; v++) x_nxt[v] = r[v];

            for (int j = 0; j < cnt; j++) {
                float a_cur = a_nxt;
                float4 x_cur[V];
#pragma unroll
                for (int v = 0; v < V; v++) x_cur[v] = x_nxt[v];
                if (j + 1 < cnt) {
                    int srn = sr_sh[warp][j + 1];
                    a_nxt = al_sh[warp][(j + 1) * H + hsel];
                    const float4* rn = (const float4*)(xbase + (size_t)srn * CH);
#pragma unroll
                    for (int v = 0; v < V; v++) x_nxt[v] = rn[v];
                }
#pragma unroll
                for (int v = 0; v < V; v++) {
                    acc[v].x += x_cur[v].x * a_cur;
                    acc[v].y += x_cur[v].y * a_cur;
                    acc[v].z += x_cur[v].z * a_cur;
                    acc[v].w += x_cur[v].w * a_cur;
                }
            }
        }
        __syncwarp();
    }

#pragma unroll
    for (int h = 0; h < H; h++)
#pragma unroll
        for (int off = 16; off; off >>= 1)
            zh[h] += __shfl_xor_sync(FULL, zh[h], off);
    float zi = 1.f / (zh[hsel] + 1e-16f);

    float4* orow = (float4*)(out + (size_t)n * CH) + lane * V;
    const float4* brow = (const float4*)bias + lane * V;
#pragma unroll
    for (int v = 0; v < V; v++) {
        float4 bv = brow[v];
        float4 r;
        r.x = acc[v].x * zi + bv.x;
        r.y = acc[v].y * zi + bv.y;
        r.z = acc[v].z * zi + bv.z;
        r.w = acc[v].w * zi + bv.w;
        if (ELU) {
            r.x = r.x > 0.f ? r.x : (__expf(r.x) - 1.f);
            r.y = r.y > 0.f ? r.y : (__expf(r.y) - 1.f);
            r.z = r.z > 0.f ? r.z : (__expf(r.z) - 1.f);
            r.w = r.w > 0.f ? r.w : (__expf(r.w) - 1.f);
        }
        orow[v] = r;
    }
}

// ---------------- launch ----------------
extern "C" void kernel_launch(void* const* d_in, const int* in_sizes, int n_in,
                              void* d_out, int out_size) {
    const float* x      = (const float*)d_in[0];
    const int*   ei     = (const int*)d_in[1];
    const float* W0     = (const float*)d_in[2];
    const float* a_src0 = (const float*)d_in[3];
    const float* a_dst0 = (const float*)d_in[4];
    const float* b0     = (const float*)d_in[5];
    const float* W1     = (const float*)d_in[6];
    const float* a_src1 = (const float*)d_in[7];
    const float* a_dst1 = (const float*)d_in[8];
    const float* b1     = (const float*)d_in[9];
    const float* W2     = (const float*)d_in[10];
    const float* a_src2 = (const float*)d_in[11];
    const float* a_dst2 = (const float*)d_in[12];
    const float* b2     = (const float*)d_in[13];

    float *bufA, *bufB, *s, *d;
    int* counts;
    cudaGetSymbolAddress((void**)&bufA, g_bufA);
    cudaGetSymbolAddress((void**)&bufB, g_bufB);
    cudaGetSymbolAddress((void**)&s, g_s);
    cudaGetSymbolAddress((void**)&d, g_d);
    cudaGetSymbolAddress((void**)&counts, g_counts);

    // CSR build + smax reset
    cudaMemsetAsync(counts, 0, NN * sizeof(int));
    k_smax_reset<<<1, 32>>>();
    k_build_count<<<(E_TOT + 255) / 256, 256>>>(ei);
    k_scan<<<1, 1024>>>();
    k_scatter<<<(E_TOT + 255) / 256, 256>>>(ei);

    dim3 gHC(256 / 64, (NN + 127) / 128);
    dim3 gO(128 / 64, (NN + 127) / 128);
    int aggBlocks = (NN + 7) / 8;

    // layer 0
    k_gemm_tc<<<gHC, 256>>>(x, W0, bufA, NN, 128, 256);
    k_scores<<<(NN * 4 * 32 + 255) / 256, 256>>>(bufA, a_src0, a_dst0, s, d, 4, 64);
    k_smax<4><<<196, 256>>>(s, 0);
    k_agg_warp<4, 64, true><<<aggBlocks, 256>>>(bufA, s, d, b0, bufB, 0);

    // layer 1
    k_gemm_tc<<<gHC, 256>>>(bufB, W1, bufA, NN, 256, 256);
    k_scores<<<(NN * 4 * 32 + 255) / 256, 256>>>(bufA, a_src1, a_dst1, s, d, 4, 64);
    k_smax<4><<<196, 256>>>(s, 4);
    k_agg_warp<4, 64, true><<<aggBlocks, 256>>>(bufA, s, d, b1, bufB, 4);

    // layer 2
    k_gemm_tc<<<gO, 256>>>(bufB, W2, bufA, NN, 256, 128);
    k_scores<<<(NN * 1 * 32 + 255) / 256, 256>>>(bufA, a_src2, a_dst2, s, d, 1, 128);
    k_smax<1><<<49, 256>>>(s, 8);
    k_agg_warp<1, 128, false><<<aggBlocks, 256>>>(bufA, s, d, b2, (float*)d_out, 8);
}

// round 15
// speedup vs baseline: 1.1413x; 1.1413x over previous
#include <cuda_runtime.h>
#include <cuda_fp16.h>
#include <math.h>
#include <stdint.h>

#define NN 50000
#define E_RAW 800000
#define E_TOT (E_RAW + NN)

// ---------------- scratch ----------------
__device__ float  g_bufA[(size_t)NN * 256];
__device__ float  g_bufB[(size_t)NN * 256];
__device__ __half g_xp_h[(size_t)NN * 256];   // fp16 mirror of GEMM output (gather source)
__device__ float  g_s[NN * 4];
__device__ float  g_d[NN * 4];
__device__ int    g_counts[NN];
__device__ int    g_row_ptr[NN + 1];
__device__ int    g_row_fill[NN];
__device__ int    g_col_src[E_TOT];
__device__ unsigned g_smax_u[12];   // 4 slots per layer

// ---------------- CSR build ----------------
__global__ void k_build_count(const int* __restrict__ ei) {
    int e = blockIdx.x * blockDim.x + threadIdx.x;
    if (e >= E_TOT) return;
    int dst = (e < E_RAW) ? ei[E_RAW + e] : (e - E_RAW);
    atomicAdd(&g_counts[dst], 1);
}

__global__ void k_scan() {
    const int CH = (NN + 1023) / 1024;
    int t = threadIdx.x;
    int lane = t & 31, warp = t >> 5;
    int beg = t * CH;
    int end = min(beg + CH, NN);
    int s = 0;
    for (int i = beg; i < end; i++) s += g_counts[i];

    int v = s;
#pragma unroll
    for (int off = 1; off < 32; off <<= 1) {
        int u = __shfl_up_sync(0xffffffffu, v, off);
        if (lane >= off) v += u;
    }
    __shared__ int wsum[32];
    if (lane == 31) wsum[warp] = v;
    __syncthreads();
    if (warp == 0) {
        int w = wsum[lane];
#pragma unroll
        for (int off = 1; off < 32; off <<= 1) {
            int u = __shfl_up_sync(0xffffffffu, w, off);
            if (lane >= off) w += u;
        }
        wsum[lane] = w;
    }
    __syncthreads();
    int excl = v - s + (warp ? wsum[warp - 1] : 0);

    int p = excl;
    for (int i = beg; i < end; i++) {
        g_row_fill[i] = p;
        p += g_counts[i];
        g_row_ptr[i + 1] = p;
    }
    if (t == 0) g_row_ptr[0] = 0;
}

__global__ void k_scatter(const int* __restrict__ ei) {
    int e = blockIdx.x * blockDim.x + threadIdx.x;
    if (e >= E_TOT) return;
    int s_, d_;
    if (e < E_RAW) { s_ = ei[e]; d_ = ei[E_RAW + e]; }
    else           { s_ = d_ = e - E_RAW; }
    int pos = atomicAdd(&g_row_fill[d_], 1);
    g_col_src[pos] = s_;
}

// ---------------- tf32 tensor-core GEMM, double-buffered (R12-proven layout) ----------------
__device__ __forceinline__ uint32_t f2tf32(float x) {
    uint32_t r;
    asm("cvt.rna.tf32.f32 %0, %1;" : "=r"(r) : "f"(x));
    return r;
}

__device__ __forceinline__ void mma_tf32(float* c, const uint32_t* a, const uint32_t* b) {
    asm volatile(
        "mma.sync.aligned.m16n8k8.row.col.f32.tf32.tf32.f32 "
        "{%0,%1,%2,%3}, {%4,%5,%6,%7}, {%8,%9}, {%0,%1,%2,%3};"
        : "+f"(c[0]), "+f"(c[1]), "+f"(c[2]), "+f"(c[3])
        : "r"(a[0]), "r"(a[1]), "r"(a[2]), "r"(a[3]), "r"(b[0]), "r"(b[1]));
}

// C[N,M] = A[N,K] @ B[K,M]; tile 128x64, K-step 32, 8 warps, double-buffered.
// Also writes fp16 mirror Ch for the aggregation gather.
__global__ void k_gemm_tc(const float* __restrict__ A, const float* __restrict__ B,
                          float* __restrict__ C, __half* __restrict__ Ch,
                          int N, int K, int M) {
    __shared__ __align__(16) uint32_t As[2][128][36];
    __shared__ __align__(16) uint32_t Bs[2][32][68];

    int tid = threadIdx.x;
    int lane = tid & 31, wid = tid >> 5;
    int warp_m = wid & 1, warp_n = wid >> 1;
    int g = lane >> 2, t = lane & 3;
    int rowBase = blockIdx.y * 128, colBase = blockIdx.x * 64;

    float acc[4][2][4] = {};
    float4 ra[4], rb[2];

    int a_r[4], a_c[4], b_r[2], b_c[2];
#pragma unroll
    for (int i = 0; i < 4; i++) {
        int idx = tid + i * 256;
        a_r[i] = idx >> 3; a_c[i] = (idx & 7) * 4;
    }
#pragma unroll
    for (int i = 0; i < 2; i++) {
        int idx = tid + i * 256;
        b_r[i] = idx >> 4; b_c[i] = (idx & 15) * 4;
    }

#define LOAD_TILE(kb)                                                              \
    {                                                                              \
        _Pragma("unroll")                                                          \
        for (int i = 0; i < 4; i++) {                                              \
            int gr = rowBase + a_r[i];                                             \
            ra[i] = (gr < N) ? *(const float4*)(A + (size_t)gr * K + (kb) + a_c[i])\
                             : make_float4(0.f, 0.f, 0.f, 0.f);                    \
        }                                                                          \
        _Pragma("unroll")                                                          \
        for (int i = 0; i < 2; i++)                                                \
            rb[i] = *(const float4*)(B + (size_t)((kb) + b_r[i]) * M + colBase + b_c[i]); \
    }

#define STORE_TILE(buf)                                                            \
    {                                                                              \
        _Pragma("unroll")                                                          \
        for (int i = 0; i < 4; i++) {                                              \
            uint4 u;                                                               \
            u.x = f2tf32(ra[i].x); u.y = f2tf32(ra[i].y);                          \
            u.z = f2tf32(ra[i].z); u.w = f2tf32(ra[i].w);                          \
            *(uint4*)&As[buf][a_r[i]][a_c[i]] = u;                                 \
        }                                                                          \
        _Pragma("unroll")                                                          \
        for (int i = 0; i < 2; i++) {                                              \
            uint4 u;                                                               \
            u.x = f2tf32(rb[i].x); u.y = f2tf32(rb[i].y);                          \
            u.z = f2tf32(rb[i].z); u.w = f2tf32(rb[i].w);                          \
            *(uint4*)&Bs[buf][b_r[i]][b_c[i]] = u;                                 \
        }                                                                          \
    }

    LOAD_TILE(0);
    STORE_TILE(0);
    __syncthreads();

    int nk = K >> 5;
    for (int ik = 0; ik < nk; ik++) {
        int cur = ik & 1;
        if (ik + 1 < nk) LOAD_TILE((ik + 1) << 5);

#pragma unroll
        for (int kk = 0; kk < 32; kk += 8) {
            uint32_t bf[2][2];
#pragma unroll
            for (int ni = 0; ni < 2; ni++) {
                int col = warp_n * 16 + ni * 8 + g;
                bf[ni][0] = Bs[cur][kk + t][col];
                bf[ni][1] = Bs[cur][kk + t + 4][col];
            }
#pragma unroll
            for (int mi = 0; mi < 4; mi++) {
                int row = warp_m * 64 + mi * 16;
                uint32_t af[4];
                af[0] = As[cur][row + g][kk + t];
                af[1] = As[cur][row + g + 8][kk + t];
                af[2] = As[cur][row + g][kk + t + 4];
                af[3] = As[cur][row + g + 8][kk + t + 4];
#pragma unroll
                for (int ni = 0; ni < 2; ni++)
                    mma_tf32(acc[mi][ni], af, bf[ni]);
            }
        }
        if (ik + 1 < nk) {
            STORE_TILE(cur ^ 1);
            __syncthreads();
        }
    }

#pragma unroll
    for (int mi = 0; mi < 4; mi++) {
#pragma unroll
        for (int ni = 0; ni < 2; ni++) {
            int r0 = rowBase + warp_m * 64 + mi * 16 + g;
            int c0 = colBase + warp_n * 16 + ni * 8 + 2 * t;
            if (r0 < N) {
                *(float2*)(C + (size_t)r0 * M + c0) = make_float2(acc[mi][ni][0], acc[mi][ni][1]);
                *(__half2*)(Ch + (size_t)r0 * M + c0) = __floats2half2_rn(acc[mi][ni][0], acc[mi][ni][1]);
            }
            if (r0 + 8 < N) {
                *(float2*)(C + (size_t)(r0 + 8) * M + c0) = make_float2(acc[mi][ni][2], acc[mi][ni][3]);
                *(__half2*)(Ch + (size_t)(r0 + 8) * M + c0) = __floats2half2_rn(acc[mi][ni][2], acc[mi][ni][3]);
            }
        }
    }
#undef LOAD_TILE
#undef STORE_TILE
}

// ---------------- per-node attention scores (fp32 xp) ----------------
__global__ void k_scores(const float* __restrict__ xp, const float* __restrict__ a_src,
                         const float* __restrict__ a_dst, float* __restrict__ s,
                         float* __restrict__ d, int H, int C) {
    int gw = (blockIdx.x * blockDim.x + threadIdx.x) >> 5;
    int lane = threadIdx.x & 31;
    if (gw >= NN * H) return;
    int n = gw / H, h = gw - n * H;
    const float* row = xp + (size_t)n * H * C + h * C;
    float ss = 0.f, dd = 0.f;
    for (int c = lane; c < C; c += 32) {
        float v = row[c];
        ss += v * a_src[h * C + c];
        dd += v * a_dst[h * C + c];
    }
#pragma unroll
    for (int off = 16; off; off >>= 1) {
        ss += __shfl_xor_sync(0xffffffffu, ss, off);
        dd += __shfl_xor_sync(0xffffffffu, dd, off);
    }
    if (lane == 0) { s[n * H + h] = ss; d[n * H + h] = dd; }
}

// ---------------- global per-head max of s ----------------
__device__ __forceinline__ unsigned f_enc(float x) {
    unsigned b = __float_as_uint(x);
    return (b & 0x80000000u) ? ~b : (b | 0x80000000u);
}
__device__ __forceinline__ float f_dec(unsigned u) {
    unsigned b = (u & 0x80000000u) ? (u & 0x7FFFFFFFu) : ~u;
    return __uint_as_float(b);
}

template <int H>
__global__ void k_smax(const float* __restrict__ s, int slot) {
    const unsigned FULL = 0xffffffffu;
    int total4 = (H == 4) ? NN : NN / 4;
    float mx[4] = {-1e30f, -1e30f, -1e30f, -1e30f};
    for (int i = blockIdx.x * blockDim.x + threadIdx.x; i < total4; i += gridDim.x * blockDim.x) {
        float4 v = ((const float4*)s)[i];
        mx[0] = fmaxf(mx[0], v.x);
        mx[1] = fmaxf(mx[1], v.y);
        mx[2] = fmaxf(mx[2], v.z);
        mx[3] = fmaxf(mx[3], v.w);
    }
    if (H == 1) {
        mx[0] = fmaxf(fmaxf(mx[0], mx[1]), fmaxf(mx[2], mx[3]));
    }
    int lane = threadIdx.x & 31;
#pragma unroll
    for (int h = 0; h < H; h++) {
#pragma unroll
        for (int off = 16; off; off >>= 1)
            mx[h] = fmaxf(mx[h], __shfl_xor_sync(FULL, mx[h], off));
        if (lane == 0) atomicMax(&g_smax_u[slot + h], f_enc(mx[h]));
    }
}

__global__ void k_smax_reset() {
    if (threadIdx.x < 12) g_smax_u[threadIdx.x] = 0u;
}

// ---------------- aggregation: one WARP per node, fp16 gather ----------------
template <int H, int C, bool ELU>
__global__ void k_agg_warp(const __half* __restrict__ xph, const float* __restrict__ sarr,
                           const float* __restrict__ darr, const float* __restrict__ bias,
                           float* __restrict__ out, int slot) {
    constexpr int CH = H * C;            // 256 or 128
    constexpr int PL = CH / 32;          // halves per lane (8 or 4)
    constexpr int NH2 = PL / 2;          // half2 per lane (4 or 2)
    const unsigned FULL = 0xffffffffu;

    __shared__ float al_sh[8][32 * H];
    __shared__ int   sr_sh[8][32];

    int warp = threadIdx.x >> 5, lane = threadIdx.x & 31;
    int n = blockIdx.x * 8 + warp;
    if (n >= NN) return;

    int beg = g_row_ptr[n];
    int deg = g_row_ptr[n + 1] - beg;

    float dn[H];
    if (H == 4) {
        float4 t4 = ((const float4*)darr)[n];
        dn[0] = t4.x; dn[1] = t4.y; dn[2] = t4.z; dn[3] = t4.w;
    } else {
        dn[0] = darr[n];
    }

    // upper-bound shift: m[h] = leaky(S_max[h] + d[n][h]) >= neighborhood max
    float mx[H];
#pragma unroll
    for (int h = 0; h < H; h++) {
        float e = f_dec(g_smax_u[slot + h]) + dn[h];
        mx[h] = e > 0.f ? e : 0.2f * e;
    }

    const int hsel = (lane * PL) / C;
    const __half* xbase = xph + lane * PL;
    float zh[H];
#pragma unroll
    for (int h = 0; h < H; h++) zh[h] = 0.f;
    float2 acc[NH2];
#pragma unroll
    for (int v = 0; v < NH2; v++) acc[v] = make_float2(0.f, 0.f);

    for (int base = 0; base < deg; base += 32) {
        int idx = base + lane;
        if (idx < deg) {
            int srl = g_col_src[beg + idx];
            sr_sh[warp][lane] = srl;
            float ev[H];
            if (H == 4) {
                float4 sv = ((const float4*)sarr)[srl];
                ev[0] = sv.x; ev[1] = sv.y; ev[2] = sv.z; ev[3] = sv.w;
            } else {
                ev[0] = sarr[srl];
            }
#pragma unroll
            for (int h = 0; h < H; h++) {
                float e = ev[h] + dn[h];
                e = e > 0.f ? e : 0.2f * e;
                float p = __expf(e - mx[h]);
                al_sh[warp][lane * H + h] = p;
                zh[h] += p;
            }
        }
        __syncwarp();
        int cnt = min(32, deg - base);

        for (int j = 0; j < cnt; j++) {
            int srj = sr_sh[warp][j];
            float aj = al_sh[warp][j * H + hsel];
            const __half* xr = xbase + (size_t)srj * CH;
            __half2 hv[NH2];
            if (NH2 == 4) {
                uint4 u = *(const uint4*)xr;
                hv[0] = *(__half2*)&u.x; hv[1] = *(__half2*)&u.y;
                hv[2] = *(__half2*)&u.z; hv[3] = *(__half2*)&u.w;
            } else {
                uint2 u = *(const uint2*)xr;
                hv[0] = *(__half2*)&u.x; hv[1] = *(__half2*)&u.y;
            }
#pragma unroll
            for (int v = 0; v < NH2; v++) {
                float2 f = __half22float2(hv[v]);
                acc[v].x += f.x * aj;
                acc[v].y += f.y * aj;
            }
        }
        __syncwarp();
    }

    // warp-reduce z, normalize, bias (+elu), store fp32
#pragma unroll
    for (int h = 0; h < H; h++)
#pragma unroll
        for (int off = 16; off; off >>= 1)
            zh[h] += __shfl_xor_sync(FULL, zh[h], off);
    float zi = 1.f / (zh[hsel] + 1e-16f);

    float* orow = out + (size_t)n * CH + lane * PL;
    const float* brow = bias + lane * PL;
#pragma unroll
    for (int v = 0; v < NH2; v++) {
        float2 r;
        r.x = acc[v].x * zi + brow[2 * v];
        r.y = acc[v].y * zi + brow[2 * v + 1];
        if (ELU) {
            r.x = r.x > 0.f ? r.x : (__expf(r.x) - 1.f);
            r.y = r.y > 0.f ? r.y : (__expf(r.y) - 1.f);
        }
        *(float2*)(orow + 2 * v) = r;
    }
}

// ---------------- launch ----------------
extern "C" void kernel_launch(void* const* d_in, const int* in_sizes, int n_in,
                              void* d_out, int out_size) {
    const float* x      = (const float*)d_in[0];
    const int*   ei     = (const int*)d_in[1];
    const float* W0     = (const float*)d_in[2];
    const float* a_src0 = (const float*)d_in[3];
    const float* a_dst0 = (const float*)d_in[4];
    const float* b0     = (const float*)d_in[5];
    const float* W1     = (const float*)d_in[6];
    const float* a_src1 = (const float*)d_in[7];
    const float* a_dst1 = (const float*)d_in[8];
    const float* b1     = (const float*)d_in[9];
    const float* W2     = (const float*)d_in[10];
    const float* a_src2 = (const float*)d_in[11];
    const float* a_dst2 = (const float*)d_in[12];
    const float* b2     = (const float*)d_in[13];

    float *bufA, *bufB, *s, *d;
    __half* xph;
    int* counts;
    cudaGetSymbolAddress((void**)&bufA, g_bufA);
    cudaGetSymbolAddress((void**)&bufB, g_bufB);
    cudaGetSymbolAddress((void**)&xph, g_xp_h);
    cudaGetSymbolAddress((void**)&s, g_s);
    cudaGetSymbolAddress((void**)&d, g_d);
    cudaGetSymbolAddress((void**)&counts, g_counts);

    // CSR build + smax reset
    cudaMemsetAsync(counts, 0, NN * sizeof(int));
    k_smax_reset<<<1, 32>>>();
    k_build_count<<<(E_TOT + 255) / 256, 256>>>(ei);
    k_scan<<<1, 1024>>>();
    k_scatter<<<(E_TOT + 255) / 256, 256>>>(ei);

    dim3 gHC(256 / 64, (NN + 127) / 128);
    dim3 gO(128 / 64, (NN + 127) / 128);
    int aggBlocks = (NN + 7) / 8;

    // layer 0
    k_gemm_tc<<<gHC, 256>>>(x, W0, bufA, xph, NN, 128, 256);
    k_scores<<<(NN * 4 * 32 + 255) / 256, 256>>>(bufA, a_src0, a_dst0, s, d, 4, 64);
    k_smax<4><<<196, 256>>>(s, 0);
    k_agg_warp<4, 64, true><<<aggBlocks, 256>>>(xph, s, d, b0, bufB, 0);

    // layer 1
    k_gemm_tc<<<gHC, 256>>>(bufB, W1, bufA, xph, NN, 256, 256);
    k_scores<<<(NN * 4 * 32 + 255) / 256, 256>>>(bufA, a_src1, a_dst1, s, d, 4, 64);
    k_smax<4><<<196, 256>>>(s, 4);
    k_agg_warp<4, 64, true><<<aggBlocks, 256>>>(xph, s, d, b1, bufB, 4);

    // layer 2
    k_gemm_tc<<<gO, 256>>>(bufB, W2, bufA, xph, NN, 256, 128);
    k_scores<<<(NN * 1 * 32 + 255) / 256, 256>>>(bufA, a_src2, a_dst2, s, d, 1, 128);
    k_smax<1><<<49, 256>>>(s, 8);
    k_agg_warp<1, 128, false><<<aggBlocks, 256>>>(xph, s, d, b2, (float*)d_out, 8);
}

// round 16
// speedup vs baseline: 1.2818x; 1.1231x over previous
#include <cuda_runtime.h>
#include <cuda_fp16.h>
#include <math.h>
#include <stdint.h>

#define NN 50000
#define E_RAW 800000
#define E_TOT (E_RAW + NN)

// ---------------- scratch ----------------
__device__ float  g_bufA[(size_t)NN * 256];
__device__ float  g_bufB[(size_t)NN * 256];
__device__ __half g_xp_h[(size_t)NN * 256];   // fp16 mirror of GEMM output (gather source)
__device__ float  g_s[NN * 4];
__device__ float  g_d[NN * 4];
__device__ int    g_counts[NN];
__device__ int    g_row_ptr[NN + 1];
__device__ int    g_row_fill[NN];
__device__ int    g_col_src[E_TOT];
__device__ unsigned g_smax_u[12];   // 4 slots per layer

// ---------------- CSR build ----------------
__global__ void k_build_count(const int* __restrict__ ei) {
    int e = blockIdx.x * blockDim.x + threadIdx.x;
    if (e >= E_TOT) return;
    int dst = (e < E_RAW) ? ei[E_RAW + e] : (e - E_RAW);
    atomicAdd(&g_counts[dst], 1);
}

__global__ void k_scan() {
    const int CH = (NN + 1023) / 1024;
    int t = threadIdx.x;
    int lane = t & 31, warp = t >> 5;
    int beg = t * CH;
    int end = min(beg + CH, NN);
    int s = 0;
    for (int i = beg; i < end; i++) s += g_counts[i];

    int v = s;
#pragma unroll
    for (int off = 1; off < 32; off <<= 1) {
        int u = __shfl_up_sync(0xffffffffu, v, off);
        if (lane >= off) v += u;
    }
    __shared__ int wsum[32];
    if (lane == 31) wsum[warp] = v;
    __syncthreads();
    if (warp == 0) {
        int w = wsum[lane];
#pragma unroll
        for (int off = 1; off < 32; off <<= 1) {
            int u = __shfl_up_sync(0xffffffffu, w, off);
            if (lane >= off) w += u;
        }
        wsum[lane] = w;
    }
    __syncthreads();
    int excl = v - s + (warp ? wsum[warp - 1] : 0);

    int p = excl;
    for (int i = beg; i < end; i++) {
        g_row_fill[i] = p;
        p += g_counts[i];
        g_row_ptr[i + 1] = p;
    }
    if (t == 0) g_row_ptr[0] = 0;
}

__global__ void k_scatter(const int* __restrict__ ei) {
    int e = blockIdx.x * blockDim.x + threadIdx.x;
    if (e >= E_TOT) return;
    int s_, d_;
    if (e < E_RAW) { s_ = ei[e]; d_ = ei[E_RAW + e]; }
    else           { s_ = d_ = e - E_RAW; }
    int pos = atomicAdd(&g_row_fill[d_], 1);
    g_col_src[pos] = s_;
}

// ---------------- fp16 tensor-core GEMM (m16n8k16), double-buffered, ldmatrix ----------------
__device__ __forceinline__ void mma_f16(float* c, const uint32_t* a, const uint32_t* b) {
    asm volatile(
        "mma.sync.aligned.m16n8k16.row.col.f32.f16.f16.f32 "
        "{%0,%1,%2,%3}, {%4,%5,%6,%7}, {%8,%9}, {%0,%1,%2,%3};"
        : "+f"(c[0]), "+f"(c[1]), "+f"(c[2]), "+f"(c[3])
        : "r"(a[0]), "r"(a[1]), "r"(a[2]), "r"(a[3]), "r"(b[0]), "r"(b[1]));
}

// C[N,M] = A[N,K] @ B[K,M]; tile 128x64, K-step 32, 8 warps, double-buffered.
// A/B staged as fp16 in smem; fragments via ldmatrix. Writes fp32 C + fp16 mirror Ch.
__global__ void k_gemm_tc(const float* __restrict__ A, const float* __restrict__ B,
                          float* __restrict__ C, __half* __restrict__ Ch,
                          int N, int K, int M) {
    __shared__ __align__(16) __half AsH[2][128][40];   // pad 40: 80B rows -> ldmatrix conflict-free
    __shared__ __align__(16) __half BsH[2][32][72];    // pad 72: 144B rows -> conflict-free

    int tid = threadIdx.x;
    int lane = tid & 31, wid = tid >> 5;
    int warp_m = wid & 1, warp_n = wid >> 1;
    int g = lane >> 2, t = lane & 3;
    int rowBase = blockIdx.y * 128, colBase = blockIdx.x * 64;

    float acc[4][2][4] = {};
    float4 ra[4], rb[2];

    int a_r[4], a_c[4], b_r[2], b_c[2];
#pragma unroll
    for (int i = 0; i < 4; i++) {
        int idx = tid + i * 256;
        a_r[i] = idx >> 3; a_c[i] = (idx & 7) * 4;
    }
#pragma unroll
    for (int i = 0; i < 2; i++) {
        int idx = tid + i * 256;
        b_r[i] = idx >> 4; b_c[i] = (idx & 15) * 4;
    }

    // per-lane ldmatrix source addresses (precomputed row/col parts)
    int lm_a_row = (lane & 7) + 8 * ((lane >> 3) & 1);  // row within 16-row frag
    int lm_a_kh  = (lane >> 4) * 8;                      // k-half select
    int lm_b_k   = lane & 15;                            // k row (lanes 16-31 mirror)

#define LOAD_TILE(kb)                                                              \
    {                                                                              \
        _Pragma("unroll")                                                          \
        for (int i = 0; i < 4; i++) {                                              \
            int gr = rowBase + a_r[i];                                             \
            ra[i] = (gr < N) ? *(const float4*)(A + (size_t)gr * K + (kb) + a_c[i])\
                             : make_float4(0.f, 0.f, 0.f, 0.f);                    \
        }                                                                          \
        _Pragma("unroll")                                                          \
        for (int i = 0; i < 2; i++)                                                \
            rb[i] = *(const float4*)(B + (size_t)((kb) + b_r[i]) * M + colBase + b_c[i]); \
    }

#define STORE_TILE(buf)                                                            \
    {                                                                              \
        _Pragma("unroll")                                                          \
        for (int i = 0; i < 4; i++) {                                              \
            __half2 h0 = __floats2half2_rn(ra[i].x, ra[i].y);                      \
            __half2 h1 = __floats2half2_rn(ra[i].z, ra[i].w);                      \
            uint2 u; u.x = *(uint32_t*)&h0; u.y = *(uint32_t*)&h1;                 \
            *(uint2*)&AsH[buf][a_r[i]][a_c[i]] = u;                                \
        }                                                                          \
        _Pragma("unroll")                                                          \
        for (int i = 0; i < 2; i++) {                                              \
            __half2 h0 = __floats2half2_rn(rb[i].x, rb[i].y);                      \
            __half2 h1 = __floats2half2_rn(rb[i].z, rb[i].w);                      \
            uint2 u; u.x = *(uint32_t*)&h0; u.y = *(uint32_t*)&h1;                 \
            *(uint2*)&BsH[buf][b_r[i]][b_c[i]] = u;                                \
        }                                                                          \
    }

    LOAD_TILE(0);
    STORE_TILE(0);
    __syncthreads();

    int nk = K >> 5;
    for (int ik = 0; ik < nk; ik++) {
        int cur = ik & 1;
        if (ik + 1 < nk) LOAD_TILE((ik + 1) << 5);

#pragma unroll
        for (int ks = 0; ks < 2; ks++) {
            int k0 = ks * 16;
            // B fragments: ldmatrix.x2.trans on [k][n] tiles
            uint32_t bf[2][2];
#pragma unroll
            for (int ni = 0; ni < 2; ni++) {
                int n0 = warp_n * 16 + ni * 8;
                uint32_t baddr = (uint32_t)__cvta_generic_to_shared(
                    &BsH[cur][k0 + lm_b_k][n0]);
                asm volatile(
                    "ldmatrix.sync.aligned.m8n8.x2.trans.shared.b16 {%0,%1}, [%2];"
                    : "=r"(bf[ni][0]), "=r"(bf[ni][1]) : "r"(baddr));
            }
#pragma unroll
            for (int mi = 0; mi < 4; mi++) {
                int row0 = warp_m * 64 + mi * 16;
                uint32_t af[4];
                uint32_t aaddr = (uint32_t)__cvta_generic_to_shared(
                    &AsH[cur][row0 + lm_a_row][k0 + lm_a_kh]);
                asm volatile(
                    "ldmatrix.sync.aligned.m8n8.x4.shared.b16 {%0,%1,%2,%3}, [%4];"
                    : "=r"(af[0]), "=r"(af[1]), "=r"(af[2]), "=r"(af[3]) : "r"(aaddr));
#pragma unroll
                for (int ni = 0; ni < 2; ni++)
                    mma_f16(acc[mi][ni], af, bf[ni]);
            }
        }
        if (ik + 1 < nk) {
            STORE_TILE(cur ^ 1);
            __syncthreads();
        }
    }

#pragma unroll
    for (int mi = 0; mi < 4; mi++) {
#pragma unroll
        for (int ni = 0; ni < 2; ni++) {
            int r0 = rowBase + warp_m * 64 + mi * 16 + g;
            int c0 = colBase + warp_n * 16 + ni * 8 + 2 * t;
            if (r0 < N) {
                *(float2*)(C + (size_t)r0 * M + c0) = make_float2(acc[mi][ni][0], acc[mi][ni][1]);
                *(__half2*)(Ch + (size_t)r0 * M + c0) = __floats2half2_rn(acc[mi][ni][0], acc[mi][ni][1]);
            }
            if (r0 + 8 < N) {
                *(float2*)(C + (size_t)(r0 + 8) * M + c0) = make_float2(acc[mi][ni][2], acc[mi][ni][3]);
                *(__half2*)(Ch + (size_t)(r0 + 8) * M + c0) = __floats2half2_rn(acc[mi][ni][2], acc[mi][ni][3]);
            }
        }
    }
#undef LOAD_TILE
#undef STORE_TILE
}

// ---------------- per-node attention scores (fp32 xp) ----------------
__global__ void k_scores(const float* __restrict__ xp, const float* __restrict__ a_src,
                         const float* __restrict__ a_dst, float* __restrict__ s,
                         float* __restrict__ d, int H, int C) {
    int gw = (blockIdx.x * blockDim.x + threadIdx.x) >> 5;
    int lane = threadIdx.x & 31;
    if (gw >= NN * H) return;
    int n = gw / H, h = gw - n * H;
    const float* row = xp + (size_t)n * H * C + h * C;
    float ss = 0.f, dd = 0.f;
    for (int c = lane; c < C; c += 32) {
        float v = row[c];
        ss += v * a_src[h * C + c];
        dd += v * a_dst[h * C + c];
    }
#pragma unroll
    for (int off = 16; off; off >>= 1) {
        ss += __shfl_xor_sync(0xffffffffu, ss, off);
        dd += __shfl_xor_sync(0xffffffffu, dd, off);
    }
    if (lane == 0) { s[n * H + h] = ss; d[n * H + h] = dd; }
}

// ---------------- global per-head max of s ----------------
__device__ __forceinline__ unsigned f_enc(float x) {
    unsigned b = __float_as_uint(x);
    return (b & 0x80000000u) ? ~b : (b | 0x80000000u);
}
__device__ __forceinline__ float f_dec(unsigned u) {
    unsigned b = (u & 0x80000000u) ? (u & 0x7FFFFFFFu) : ~u;
    return __uint_as_float(b);
}

template <int H>
__global__ void k_smax(const float* __restrict__ s, int slot) {
    const unsigned FULL = 0xffffffffu;
    int total4 = (H == 4) ? NN : NN / 4;
    float mx[4] = {-1e30f, -1e30f, -1e30f, -1e30f};
    for (int i = blockIdx.x * blockDim.x + threadIdx.x; i < total4; i += gridDim.x * blockDim.x) {
        float4 v = ((const float4*)s)[i];
        mx[0] = fmaxf(mx[0], v.x);
        mx[1] = fmaxf(mx[1], v.y);
        mx[2] = fmaxf(mx[2], v.z);
        mx[3] = fmaxf(mx[3], v.w);
    }
    if (H == 1) {
        mx[0] = fmaxf(fmaxf(mx[0], mx[1]), fmaxf(mx[2], mx[3]));
    }
    int lane = threadIdx.x & 31;
#pragma unroll
    for (int h = 0; h < H; h++) {
#pragma unroll
        for (int off = 16; off; off >>= 1)
            mx[h] = fmaxf(mx[h], __shfl_xor_sync(FULL, mx[h], off));
        if (lane == 0) atomicMax(&g_smax_u[slot + h], f_enc(mx[h]));
    }
}

__global__ void k_smax_reset() {
    if (threadIdx.x < 12) g_smax_u[threadIdx.x] = 0u;
}

// ---------------- aggregation: one WARP per node, fp16 gather ----------------
template <int H, int C, bool ELU>
__global__ void k_agg_warp(const __half* __restrict__ xph, const float* __restrict__ sarr,
                           const float* __restrict__ darr, const float* __restrict__ bias,
                           float* __restrict__ out, int slot) {
    constexpr int CH = H * C;            // 256 or 128
    constexpr int PL = CH / 32;          // halves per lane (8 or 4)
    constexpr int NH2 = PL / 2;          // half2 per lane (4 or 2)
    const unsigned FULL = 0xffffffffu;

    __shared__ float al_sh[8][32 * H];
    __shared__ int   sr_sh[8][32];

    int warp = threadIdx.x >> 5, lane = threadIdx.x & 31;
    int n = blockIdx.x * 8 + warp;
    if (n >= NN) return;

    int beg = g_row_ptr[n];
    int deg = g_row_ptr[n + 1] - beg;

    float dn[H];
    if (H == 4) {
        float4 t4 = ((const float4*)darr)[n];
        dn[0] = t4.x; dn[1] = t4.y; dn[2] = t4.z; dn[3] = t4.w;
    } else {
        dn[0] = darr[n];
    }

    // upper-bound shift: m[h] = leaky(S_max[h] + d[n][h]) >= neighborhood max
    float mx[H];
#pragma unroll
    for (int h = 0; h < H; h++) {
        float e = f_dec(g_smax_u[slot + h]) + dn[h];
        mx[h] = e > 0.f ? e : 0.2f * e;
    }

    const int hsel = (lane * PL) / C;
    const __half* xbase = xph + lane * PL;
    float zh[H];
#pragma unroll
    for (int h = 0; h < H; h++) zh[h] = 0.f;
    float2 acc[NH2];
#pragma unroll
    for (int v = 0; v < NH2; v++) acc[v] = make_float2(0.f, 0.f);

    for (int base = 0; base < deg; base += 32) {
        int idx = base + lane;
        if (idx < deg) {
            int srl = g_col_src[beg + idx];
            sr_sh[warp][lane] = srl;
            float ev[H];
            if (H == 4) {
                float4 sv = ((const float4*)sarr)[srl];
                ev[0] = sv.x; ev[1] = sv.y; ev[2] = sv.z; ev[3] = sv.w;
            } else {
                ev[0] = sarr[srl];
            }
#pragma unroll
            for (int h = 0; h < H; h++) {
                float e = ev[h] + dn[h];
                e = e > 0.f ? e : 0.2f * e;
                float p = __expf(e - mx[h]);
                al_sh[warp][lane * H + h] = p;
                zh[h] += p;
            }
        }
        __syncwarp();
        int cnt = min(32, deg - base);

        for (int j = 0; j < cnt; j++) {
            int srj = sr_sh[warp][j];
            float aj = al_sh[warp][j * H + hsel];
            const __half* xr = xbase + (size_t)srj * CH;
            __half2 hv[NH2];
            if (NH2 == 4) {
                uint4 u = *(const uint4*)xr;
                hv[0] = *(__half2*)&u.x; hv[1] = *(__half2*)&u.y;
                hv[2] = *(__half2*)&u.z; hv[3] = *(__half2*)&u.w;
            } else {
                uint2 u = *(const uint2*)xr;
                hv[0] = *(__half2*)&u.x; hv[1] = *(__half2*)&u.y;
            }
#pragma unroll
            for (int v = 0; v < NH2; v++) {
                float2 f = __half22float2(hv[v]);
                acc[v].x += f.x * aj;
                acc[v].y += f.y * aj;
            }
        }
        __syncwarp();
    }

    // warp-reduce z, normalize, bias (+elu), store fp32
#pragma unroll
    for (int h = 0; h < H; h++)
#pragma unroll
        for (int off = 16; off; off >>= 1)
            zh[h] += __shfl_xor_sync(FULL, zh[h], off);
    float zi = 1.f / (zh[hsel] + 1e-16f);

    float* orow = out + (size_t)n * CH + lane * PL;
    const float* brow = bias + lane * PL;
#pragma unroll
    for (int v = 0; v < NH2; v++) {
        float2 r;
        r.x = acc[v].x * zi + brow[2 * v];
        r.y = acc[v].y * zi + brow[2 * v + 1];
        if (ELU) {
            r.x = r.x > 0.f ? r.x : (__expf(r.x) - 1.f);
            r.y = r.y > 0.f ? r.y : (__expf(r.y) - 1.f);
        }
        *(float2*)(orow + 2 * v) = r;
    }
}

// ---------------- launch ----------------
extern "C" void kernel_launch(void* const* d_in, const int* in_sizes, int n_in,
                              void* d_out, int out_size) {
    const float* x      = (const float*)d_in[0];
    const int*   ei     = (const int*)d_in[1];
    const float* W0     = (const float*)d_in[2];
    const float* a_src0 = (const float*)d_in[3];
    const float* a_dst0 = (const float*)d_in[4];
    const float* b0     = (const float*)d_in[5];
    const float* W1     = (const float*)d_in[6];
    const float* a_src1 = (const float*)d_in[7];
    const float* a_dst1 = (const float*)d_in[8];
    const float* b1     = (const float*)d_in[9];
    const float* W2     = (const float*)d_in[10];
    const float* a_src2 = (const float*)d_in[11];
    const float* a_dst2 = (const float*)d_in[12];
    const float* b2     = (const float*)d_in[13];

    float *bufA, *bufB, *s, *d;
    __half* xph;
    int* counts;
    cudaGetSymbolAddress((void**)&bufA, g_bufA);
    cudaGetSymbolAddress((void**)&bufB, g_bufB);
    cudaGetSymbolAddress((void**)&xph, g_xp_h);
    cudaGetSymbolAddress((void**)&s, g_s);
    cudaGetSymbolAddress((void**)&d, g_d);
    cudaGetSymbolAddress((void**)&counts, g_counts);

    // CSR build + smax reset
    cudaMemsetAsync(counts, 0, NN * sizeof(int));
    k_smax_reset<<<1, 32>>>();
    k_build_count<<<(E_TOT + 255) / 256, 256>>>(ei);
    k_scan<<<1, 1024>>>();
    k_scatter<<<(E_TOT + 255) / 256, 256>>>(ei);

    dim3 gHC(256 / 64, (NN + 127) / 128);
    dim3 gO(128 / 64, (NN + 127) / 128);
    int aggBlocks = (NN + 7) / 8;

    // layer 0
    k_gemm_tc<<<gHC, 256>>>(x, W0, bufA, xph, NN, 128, 256);
    k_scores<<<(NN * 4 * 32 + 255) / 256, 256>>>(bufA, a_src0, a_dst0, s, d, 4, 64);
    k_smax<4><<<196, 256>>>(s, 0);
    k_agg_warp<4, 64, true><<<aggBlocks, 256>>>(xph, s, d, b0, bufB, 0);

    // layer 1
    k_gemm_tc<<<gHC, 256>>>(bufB, W1, bufA, xph, NN, 256, 256);
    k_scores<<<(NN * 4 * 32 + 255) / 256, 256>>>(bufA, a_src1, a_dst1, s, d, 4, 64);
    k_smax<4><<<196, 256>>>(s, 4);
    k_agg_warp<4, 64, true><<<aggBlocks, 256>>>(xph, s, d, b1, bufB, 4);

    // layer 2
    k_gemm_tc<<<gO, 256>>>(bufB, W2, bufA, xph, NN, 256, 128);
    k_scores<<<(NN * 1 * 32 + 255) / 256, 256>>>(bufA, a_src2, a_dst2, s, d, 1, 128);
    k_smax<1><<<49, 256>>>(s, 8);
    k_agg_warp<1, 128, false><<<aggBlocks, 256>>>(xph, s, d, b2, (float*)d_out, 8);
}